// round 4
// baseline (speedup 1.0000x reference)
#include <cuda_runtime.h>
#include <cuda_bf16.h>
#include <math.h>
#include <stdint.h>

#define NROWS 8192
#define DIM   1024
#define TM    256
#define TN    128
#define BK    64                              // fp8 elements (= bytes) per chunk
#define NSTAGE 4
#define NITER (DIM / BK)                      // 16
#define JT    (NROWS / TN)                    // 64
#define STAGE_A_BYTES (TM * BK)               // 16384
#define STAGE_B_BYTES (TN * BK)               // 8192
#define STAGE_BYTES   (STAGE_A_BYTES + STAGE_B_BYTES)
#define SMEM_TOTAL    (NSTAGE * STAGE_BYTES)  // 98304
#define SCALE   16.0f
#define INVSCALE (1.0f / 256.0f)

// ---------------- device scratch ----------------
__device__ __align__(1024) uint8_t g_zf8[2 * NROWS * DIM];  // pre-normalized e4m3, x16
__device__ float g_inv[2 * NROWS];
__device__ float g_diag[NROWS];
__device__ float g_pe[(size_t)JT * NROWS];
__device__ float g_bl[NROWS / 128];
__device__ float g_bp[NROWS / 128];

// ---------------- PTX helpers ----------------
__device__ __forceinline__ uint32_t smem_u32(const void* p) {
    uint32_t a;
    asm("{ .reg .u64 t; cvta.to.shared.u64 t, %1; cvt.u32.u64 %0, t; }" : "=r"(a) : "l"(p));
    return a;
}
#define CPA16(dst, src) \
    asm volatile("cp.async.cg.shared.global [%0], [%1], 16;" :: "r"(dst), "l"(src) : "memory")
#define CPA_COMMIT() asm volatile("cp.async.commit_group;" ::: "memory")
#define CPA_WAIT2()  asm volatile("cp.async.wait_group 2;" ::: "memory")

__device__ __forceinline__ void ldsm4(uint32_t* r, uint32_t addr) {
    asm volatile("ldmatrix.sync.aligned.m8n8.x4.shared.b16 {%0,%1,%2,%3}, [%4];"
        : "=r"(r[0]), "=r"(r[1]), "=r"(r[2]), "=r"(r[3]) : "r"(addr));
}
__device__ __forceinline__ void mma_fp8(float* d, const uint32_t* a, const uint32_t* b) {
    asm volatile(
        "mma.sync.aligned.m16n8k32.row.col.f32.e4m3.e4m3.f32 "
        "{%0,%1,%2,%3}, {%4,%5,%6,%7}, {%8,%9}, {%0,%1,%2,%3};"
        : "+f"(d[0]), "+f"(d[1]), "+f"(d[2]), "+f"(d[3])
        : "r"(a[0]), "r"(a[1]), "r"(a[2]), "r"(a[3]), "r"(b[0]), "r"(b[1]));
}

// ---------------------------------------------------------------------------
// 1) Row inverse norms
// ---------------------------------------------------------------------------
__global__ void norms_kernel(const float* __restrict__ z) {
    int warp = threadIdx.x >> 5, lane = threadIdx.x & 31;
    int row  = blockIdx.x * 8 + warp;
    const float* p = z + (size_t)row * DIM;
    float s = 0.f;
    #pragma unroll
    for (int k = lane * 4; k < DIM; k += 128) {
        float4 v = *reinterpret_cast<const float4*>(p + k);
        s += v.x * v.x + v.y * v.y + v.z * v.z + v.w * v.w;
    }
    #pragma unroll
    for (int o = 16; o; o >>= 1) s += __shfl_xor_sync(0xffffffffu, s, o);
    if (lane == 0) g_inv[row] = rsqrtf(s);
}

// ---------------------------------------------------------------------------
// 2) Convert to pre-normalized, 16x-scaled e4m3
// ---------------------------------------------------------------------------
__global__ void convert_kernel(const float* __restrict__ z) {
    size_t i = (size_t)(blockIdx.x * blockDim.x + threadIdx.x) * 4;
    float4 v = *reinterpret_cast<const float4*>(z + i);
    float s = g_inv[i >> 10] * SCALE;
    uint16_t p0, p1;
    asm("cvt.rn.satfinite.e4m3x2.f32 %0, %1, %2;" : "=h"(p0) : "f"(v.y * s), "f"(v.x * s));
    asm("cvt.rn.satfinite.e4m3x2.f32 %0, %1, %2;" : "=h"(p1) : "f"(v.w * s), "f"(v.z * s));
    *reinterpret_cast<uint32_t*>(g_zf8 + i) = (uint32_t)p0 | ((uint32_t)p1 << 16);
}

// ---------------------------------------------------------------------------
// 3) FP8 MMA GEMM 256x128x64, 4-stage cp.async, fused exp epilogue
//    8 warps (4x2 grid), warp tile 64x64.
// ---------------------------------------------------------------------------
__global__ __launch_bounds__(256, 1) void gemm_kernel() {
    extern __shared__ char smem[];
    const uint32_t sb = smem_u32(smem);
    const int tid = threadIdx.x;
    const int warp = tid >> 5, lane = tid & 31;
    const int wy = warp >> 1, wx = warp & 1;        // 4 x 2 warp grid
    const int bi = blockIdx.y, bj = blockIdx.x;

    const char* Ag = (const char*)(g_zf8 + (size_t)bi * TM * DIM);
    const char* Bg = (const char*)(g_zf8 + (size_t)(NROWS + bj * TN) * DIM);

    // cp.async mapping: 64B rows, 4 chunks of 16B; phys = ch ^ ((row>>1)&3)
    const int row0 = tid >> 2, ch0 = tid & 3;
    const int ph0  = ch0 ^ ((row0 >> 1) & 3);
    const uint32_t s_off0 = row0 * 64 + ph0 * 16;          // same phys for row0+64k
    const size_t   g_off0 = (size_t)row0 * DIM + ch0 * 16; // bytes (1 B/elem)
    const size_t   g_r64  = (size_t)64 * DIM;

    float acc[4][8][4];
    #pragma unroll
    for (int mt = 0; mt < 4; mt++)
        #pragma unroll
        for (int nt = 0; nt < 8; nt++)
            #pragma unroll
            for (int q = 0; q < 4; q++) acc[mt][nt][q] = 0.f;

    // prologue: stages 0..2
    #pragma unroll
    for (int s = 0; s < NSTAGE - 1; s++) {
        uint32_t As = sb + s * STAGE_BYTES;
        uint32_t Bs = As + STAGE_A_BYTES;
        size_t kb = (size_t)(s * BK);
        #pragma unroll
        for (int r = 0; r < 4; r++)
            CPA16(As + s_off0 + r * 64 * 64, Ag + g_off0 + r * g_r64 + kb);
        #pragma unroll
        for (int r = 0; r < 2; r++)
            CPA16(Bs + s_off0 + r * 64 * 64, Bg + g_off0 + r * g_r64 + kb);
        CPA_COMMIT();
    }

    // ldmatrix lane components
    const int rl  = lane & 15;                 // A row within 16
    const int ahi = lane >> 4;                 // A 16B-chunk select
    const int asw = (rl >> 1) & 3;
    const int nl  = (lane & 7) | ((lane >> 4) << 3);   // B n within 16
    const int bhi = (lane >> 3) & 1;
    const int bsw = (nl >> 1) & 3;

    for (int kc = 0; kc < NITER; kc++) {
        const int st = kc & (NSTAGE - 1);
        CPA_WAIT2();
        __syncthreads();
        if (kc + NSTAGE - 1 < NITER) {
            const int sn = (kc + NSTAGE - 1) & (NSTAGE - 1);
            uint32_t As = sb + sn * STAGE_BYTES;
            uint32_t Bs = As + STAGE_A_BYTES;
            size_t kb = (size_t)((kc + NSTAGE - 1) * BK);
            #pragma unroll
            for (int r = 0; r < 4; r++)
                CPA16(As + s_off0 + r * 64 * 64, Ag + g_off0 + r * g_r64 + kb);
            #pragma unroll
            for (int r = 0; r < 2; r++)
                CPA16(Bs + s_off0 + r * 64 * 64, Bg + g_off0 + r * g_r64 + kb);
            CPA_COMMIT();
        }
        const uint32_t As = sb + st * STAGE_BYTES;
        const uint32_t Bs = As + STAGE_A_BYTES;
        #pragma unroll
        for (int ks = 0; ks < 2; ks++) {
            uint32_t a[4][4], b[4][4];
            uint32_t a_addr = As + (wy * 64 + rl) * 64 + (((ks * 2 + ahi) ^ asw) * 16);
            #pragma unroll
            for (int mt = 0; mt < 4; mt++) ldsm4(a[mt], a_addr + mt * 1024);
            uint32_t b_addr = Bs + (wx * 64 + nl) * 64 + (((ks * 2 + bhi) ^ bsw) * 16);
            #pragma unroll
            for (int p = 0; p < 4; p++) ldsm4(b[p], b_addr + p * 1024);
            #pragma unroll
            for (int mt = 0; mt < 4; mt++)
                #pragma unroll
                for (int nt = 0; nt < 8; nt++)
                    mma_fp8(acc[mt][nt], a[mt], &b[nt >> 1][(nt & 1) * 2]);
        }
        __syncthreads();
    }

    // ---------------- epilogue: rescale, exp row-sums + diagonal ----------------
    __syncthreads();
    float* sred = (float*)smem;                // 256 rows x 2 wx
    const bool isdiag = ((bj >> 1) == bi);
    #pragma unroll
    for (int mt = 0; mt < 4; mt++) {
        int ra = wy * 64 + mt * 16 + (lane >> 2);
        int gr = bi * TM + ra;
        float sA = 0.f, sB = 0.f;
        #pragma unroll
        for (int nt = 0; nt < 8; nt++) {
            int gc = bj * TN + wx * 64 + nt * 8 + 2 * (lane & 3);
            float v0 = acc[mt][nt][0] * INVSCALE, v1 = acc[mt][nt][1] * INVSCALE;
            float v2 = acc[mt][nt][2] * INVSCALE, v3 = acc[mt][nt][3] * INVSCALE;
            sA += __expf(v0) + __expf(v1);
            sB += __expf(v2) + __expf(v3);
            if (isdiag) {
                if (gr == gc)         g_diag[gr] = v0;
                if (gr == gc + 1)     g_diag[gr] = v1;
                if (gr + 8 == gc)     g_diag[gr + 8] = v2;
                if (gr + 8 == gc + 1) g_diag[gr + 8] = v3;
            }
        }
        sA += __shfl_xor_sync(0xffffffffu, sA, 1);
        sA += __shfl_xor_sync(0xffffffffu, sA, 2);
        sB += __shfl_xor_sync(0xffffffffu, sB, 1);
        sB += __shfl_xor_sync(0xffffffffu, sB, 2);
        if ((lane & 3) == 0) {
            sred[ra * 2 + wx] = sA;
            sred[(ra + 8) * 2 + wx] = sB;
        }
    }
    __syncthreads();
    {
        float s = sred[tid * 2 + 0] + sred[tid * 2 + 1];
        g_pe[(size_t)bj * NROWS + bi * TM + tid] = s;
    }
}

// ---------------------------------------------------------------------------
// 4) Finalize (ALPHA=1 -> alpha=p_ij, BETA=0 -> neg_sim drops)
// ---------------------------------------------------------------------------
__global__ void finalize1_kernel() {
    int r = blockIdx.x * 128 + threadIdx.x;
    float se = 0.f;
    #pragma unroll 8
    for (int t = 0; t < JT; t++) se += g_pe[(size_t)t * NROWS + r];
    float pos = g_diag[r];
    float pe  = __expf(pos);                   // bitwise-identical to epilogue term
    float p   = pe / (se - pe);
    float loss = -logf(p) - p * pos;

    __shared__ float sl[128], sp[128];
    sl[threadIdx.x] = loss;
    sp[threadIdx.x] = p;
    __syncthreads();
    #pragma unroll
    for (int o = 64; o; o >>= 1) {
        if (threadIdx.x < o) {
            sl[threadIdx.x] += sl[threadIdx.x + o];
            sp[threadIdx.x] += sp[threadIdx.x + o];
        }
        __syncthreads();
    }
    if (threadIdx.x == 0) { g_bl[blockIdx.x] = sl[0]; g_bp[blockIdx.x] = sp[0]; }
}

__global__ void finalize2_kernel(float* __restrict__ out) {
    __shared__ float sl[64], sp[64];
    int t = threadIdx.x;
    sl[t] = g_bl[t];
    sp[t] = g_bp[t];
    __syncthreads();
    #pragma unroll
    for (int o = 32; o; o >>= 1) {
        if (t < o) { sl[t] += sl[t + o]; sp[t] += sp[t + o]; }
        __syncthreads();
    }
    if (t == 0) {
        out[0] = sl[0] / (float)NROWS;
        out[1] = sp[0] / (float)NROWS;
    }
}

// ---------------------------------------------------------------------------
extern "C" void kernel_launch(void* const* d_in, const int* in_sizes, int n_in,
                              void* d_out, int out_size) {
    const float* z = (const float*)d_in[0];
    float* out = (float*)d_out;

    cudaFuncSetAttribute(gemm_kernel, cudaFuncAttributeMaxDynamicSharedMemorySize, SMEM_TOTAL);

    norms_kernel<<<2 * NROWS / 8, 256>>>(z);
    convert_kernel<<<(2 * NROWS * DIM / 4) / 256, 256>>>(z);
    gemm_kernel<<<dim3(NROWS / TN, NROWS / TM), 256, SMEM_TOTAL>>>();
    finalize1_kernel<<<NROWS / 128, 128>>>();
    finalize2_kernel<<<1, 64>>>(out);
}

// round 5
// speedup vs baseline: 1.3494x; 1.3494x over previous
#include <cuda_runtime.h>
#include <cuda_bf16.h>
#include <math.h>
#include <stdint.h>

#define NROWS 8192
#define DIM   1024
#define BM    128
#define BN    128
#define BK    64                              // bf16 elems per chunk (128 B rows)
#define NSTAGE 3
#define NITER (DIM / BK)                      // 16
#define JT    (NROWS / BN)                    // 64
#define STAGE_A_BYTES (BM * BK * 2)           // 16384
#define STAGE_BYTES   (2 * STAGE_A_BYTES)     // 32768
#define SMEM_TOTAL    (NSTAGE * STAGE_BYTES)  // 98304

// ---------------- device scratch ----------------
__device__ __align__(1024) __nv_bfloat16 g_zb[2 * NROWS * DIM];
__device__ float g_diag[NROWS];
__device__ float g_pe[(size_t)JT * NROWS];
__device__ float g_bl[NROWS / 128];
__device__ float g_bp[NROWS / 128];

// ---------------- PTX helpers ----------------
__device__ __forceinline__ uint32_t smem_u32(const void* p) {
    uint32_t a;
    asm("{ .reg .u64 t; cvta.to.shared.u64 t, %1; cvt.u32.u64 %0, t; }" : "=r"(a) : "l"(p));
    return a;
}
#define CPA16(dst, src) \
    asm volatile("cp.async.cg.shared.global [%0], [%1], 16;" :: "r"(dst), "l"(src) : "memory")
#define CPA_COMMIT() asm volatile("cp.async.commit_group;" ::: "memory")
#define CPA_WAIT1()  asm volatile("cp.async.wait_group 1;" ::: "memory")
#define CPA_WAIT0()  asm volatile("cp.async.wait_group 0;" ::: "memory")

__device__ __forceinline__ void ldsm4(uint32_t* r, uint32_t addr) {
    asm volatile("ldmatrix.sync.aligned.m8n8.x4.shared.b16 {%0,%1,%2,%3}, [%4];"
        : "=r"(r[0]), "=r"(r[1]), "=r"(r[2]), "=r"(r[3]) : "r"(addr));
}
__device__ __forceinline__ void mma16816(float* d, const uint32_t* a, const uint32_t* b) {
    asm volatile(
        "mma.sync.aligned.m16n8k16.row.col.f32.bf16.bf16.f32 "
        "{%0,%1,%2,%3}, {%4,%5,%6,%7}, {%8,%9}, {%0,%1,%2,%3};"
        : "+f"(d[0]), "+f"(d[1]), "+f"(d[2]), "+f"(d[3])
        : "r"(a[0]), "r"(a[1]), "r"(a[2]), "r"(a[3]), "r"(b[0]), "r"(b[1]));
}

// ---------------------------------------------------------------------------
// 1) Fused norms + convert: one warp per row, row held in registers.
// ---------------------------------------------------------------------------
__global__ __launch_bounds__(256) void normconv_kernel(const float* __restrict__ z) {
    int warp = threadIdx.x >> 5, lane = threadIdx.x & 31;
    int row  = blockIdx.x * 8 + warp;
    const float* p = z + (size_t)row * DIM;
    float4 v[8];
    float s = 0.f;
    #pragma unroll
    for (int i = 0; i < 8; i++) {
        v[i] = *reinterpret_cast<const float4*>(p + lane * 4 + i * 128);
        s += v[i].x * v[i].x + v[i].y * v[i].y + v[i].z * v[i].z + v[i].w * v[i].w;
    }
    #pragma unroll
    for (int o = 16; o; o >>= 1) s += __shfl_xor_sync(0xffffffffu, s, o);
    float inv = rsqrtf(s);
    __nv_bfloat16* ob = g_zb + (size_t)row * DIM;
    #pragma unroll
    for (int i = 0; i < 8; i++) {
        __nv_bfloat162 lo = __floats2bfloat162_rn(v[i].x * inv, v[i].y * inv);
        __nv_bfloat162 hi = __floats2bfloat162_rn(v[i].z * inv, v[i].w * inv);
        uint2 pk;
        pk.x = *reinterpret_cast<uint32_t*>(&lo);
        pk.y = *reinterpret_cast<uint32_t*>(&hi);
        *reinterpret_cast<uint2*>(ob + lane * 4 + i * 128) = pk;
    }
}

// ---------------------------------------------------------------------------
// 2) HMMA GEMM 128x128x64/iter, 3-stage cp.async, single sync per iter,
//    fused exp epilogue. 8 warps in 2x4 grid, warp tile 64x32.
// ---------------------------------------------------------------------------
__global__ __launch_bounds__(256, 2) void gemm_kernel() {
    extern __shared__ char smem[];
    const uint32_t sb = smem_u32(smem);
    const int tid = threadIdx.x;
    const int warp = tid >> 5, lane = tid & 31;
    const int wy = warp >> 2, wx = warp & 3;        // 2 x 4 warp grid
    const int bi = blockIdx.y, bj = blockIdx.x;

    const char* Ag = (const char*)(g_zb + (size_t)bi * BM * DIM);
    const char* Bg = (const char*)(g_zb + (size_t)(NROWS + bj * BN) * DIM);

    // cp.async mapping: 128B rows = 8 x 16B chunks; phys = ch ^ (row & 7).
    // Per thread: 4 chunks of A + 4 chunks of B per stage.
    const int row0 = tid >> 3, ch0 = tid & 7;       // rows 0..31
    uint32_t s_off[4];
    size_t   g_off[4];
    #pragma unroll
    for (int r = 0; r < 4; r++) {
        int row = row0 + r * 32;
        int ph  = ch0 ^ (row & 7);
        s_off[r] = row * 128 + ph * 16;
        g_off[r] = (size_t)row * DIM * 2 + ch0 * 16;
    }

    float acc[4][4][4];
    #pragma unroll
    for (int mt = 0; mt < 4; mt++)
        #pragma unroll
        for (int nt = 0; nt < 4; nt++)
            #pragma unroll
            for (int q = 0; q < 4; q++) acc[mt][nt][q] = 0.f;

    // prologue: stages 0,1 (chunks 0,1)
    #pragma unroll
    for (int s = 0; s < NSTAGE - 1; s++) {
        uint32_t As = sb + s * STAGE_BYTES;
        uint32_t Bs = As + STAGE_A_BYTES;
        size_t kb = (size_t)(s * BK) * 2;
        #pragma unroll
        for (int r = 0; r < 4; r++) {
            CPA16(As + s_off[r], Ag + g_off[r] + kb);
            CPA16(Bs + s_off[r], Bg + g_off[r] + kb);
        }
        CPA_COMMIT();
    }

    // ldmatrix lane components
    const int rl  = lane & 15;                  // A row within 16
    const int ahi = lane >> 4;                  // A 16B k-chunk select
    const int nl  = (lane & 7) | ((lane >> 4) << 3);   // B n within 16
    const int bhi = (lane >> 3) & 1;

    for (int kc = 0; kc < NITER; kc++) {
        const int st = kc % NSTAGE;
        if (kc < NITER - 1) { CPA_WAIT1(); } else { CPA_WAIT0(); }
        __syncthreads();
        if (kc + NSTAGE - 1 < NITER) {
            const int sn = (kc + NSTAGE - 1) % NSTAGE;
            uint32_t As = sb + sn * STAGE_BYTES;
            uint32_t Bs = As + STAGE_A_BYTES;
            size_t kb = (size_t)((kc + NSTAGE - 1) * BK) * 2;
            #pragma unroll
            for (int r = 0; r < 4; r++) {
                CPA16(As + s_off[r], Ag + g_off[r] + kb);
                CPA16(Bs + s_off[r], Bg + g_off[r] + kb);
            }
            CPA_COMMIT();
        }
        const uint32_t As = sb + st * STAGE_BYTES;
        const uint32_t Bs = As + STAGE_A_BYTES;
        #pragma unroll
        for (int ks = 0; ks < 4; ks++) {
            uint32_t a[4][4], b[2][4];
            uint32_t a_addr = As + (wy * 64 + rl) * 128 + (((ks * 2 + ahi) ^ (rl & 7)) * 16);
            #pragma unroll
            for (int mt = 0; mt < 4; mt++) ldsm4(a[mt], a_addr + mt * 2048);
            uint32_t b_addr = Bs + (wx * 32 + nl) * 128 + (((ks * 2 + bhi) ^ (nl & 7)) * 16);
            #pragma unroll
            for (int p = 0; p < 2; p++) ldsm4(b[p], b_addr + p * 2048);
            #pragma unroll
            for (int mt = 0; mt < 4; mt++)
                #pragma unroll
                for (int nt = 0; nt < 4; nt++)
                    mma16816(acc[mt][nt], a[mt], &b[nt >> 1][(nt & 1) * 2]);
        }
    }

    // ---------------- epilogue: exp row-sums + diagonal ----------------
    __syncthreads();
    float* sred = (float*)smem;                // 128 rows x 4 wx
    const bool isdiag = (bi == bj);
    #pragma unroll
    for (int mt = 0; mt < 4; mt++) {
        int ra = wy * 64 + mt * 16 + (lane >> 2);
        float sA = 0.f, sB = 0.f;
        #pragma unroll
        for (int nt = 0; nt < 4; nt++) {
            int c0 = wx * 32 + nt * 8 + 2 * (lane & 3);
            float v0 = acc[mt][nt][0], v1 = acc[mt][nt][1];
            float v2 = acc[mt][nt][2], v3 = acc[mt][nt][3];
            sA += __expf(v0) + __expf(v1);
            sB += __expf(v2) + __expf(v3);
            if (isdiag) {
                if (ra == c0)         g_diag[bi * BM + ra] = v0;
                if (ra == c0 + 1)     g_diag[bi * BM + ra] = v1;
                if (ra + 8 == c0)     g_diag[bi * BM + ra + 8] = v2;
                if (ra + 8 == c0 + 1) g_diag[bi * BM + ra + 8] = v3;
            }
        }
        sA += __shfl_xor_sync(0xffffffffu, sA, 1);
        sA += __shfl_xor_sync(0xffffffffu, sA, 2);
        sB += __shfl_xor_sync(0xffffffffu, sB, 1);
        sB += __shfl_xor_sync(0xffffffffu, sB, 2);
        if ((lane & 3) == 0) {
            sred[ra * 4 + wx] = sA;
            sred[(ra + 8) * 4 + wx] = sB;
        }
    }
    __syncthreads();
    if (tid < BM) {
        float s = sred[tid * 4 + 0] + sred[tid * 4 + 1]
                + sred[tid * 4 + 2] + sred[tid * 4 + 3];
        g_pe[(size_t)bj * NROWS + bi * BM + tid] = s;
    }
}

// ---------------------------------------------------------------------------
// 3) Finalize (ALPHA=1 -> alpha=p_ij, BETA=0 -> neg_sim drops).
//    1024 threads: 8-way parallel K-sum over jtiles, then row math + reduce.
// ---------------------------------------------------------------------------
__global__ __launch_bounds__(1024) void finalize1_kernel() {
    __shared__ float spart[8][128];
    __shared__ float sl[128], sp[128];
    int rl = threadIdx.x & 127, tg = threadIdx.x >> 7;
    int r = blockIdx.x * 128 + rl;
    float se = 0.f;
    #pragma unroll
    for (int t = tg * 8; t < tg * 8 + 8; t++) se += g_pe[(size_t)t * NROWS + r];
    spart[tg][rl] = se;
    __syncthreads();
    if (threadIdx.x < 128) {
        float tot = 0.f;
        #pragma unroll
        for (int t = 0; t < 8; t++) tot += spart[t][rl];
        float pos = g_diag[r];
        float pe  = __expf(pos);               // bitwise-identical to epilogue term
        float p   = pe / (tot - pe);
        sl[rl] = -logf(p) - p * pos;
        sp[rl] = p;
    }
    __syncthreads();
    #pragma unroll
    for (int o = 64; o; o >>= 1) {
        if (threadIdx.x < o) {
            sl[threadIdx.x] += sl[threadIdx.x + o];
            sp[threadIdx.x] += sp[threadIdx.x + o];
        }
        __syncthreads();
    }
    if (threadIdx.x == 0) { g_bl[blockIdx.x] = sl[0]; g_bp[blockIdx.x] = sp[0]; }
}

__global__ void finalize2_kernel(float* __restrict__ out) {
    __shared__ float sl[64], sp[64];
    int t = threadIdx.x;
    sl[t] = g_bl[t];
    sp[t] = g_bp[t];
    __syncthreads();
    #pragma unroll
    for (int o = 32; o; o >>= 1) {
        if (t < o) { sl[t] += sl[t + o]; sp[t] += sp[t + o]; }
        __syncthreads();
    }
    if (t == 0) {
        out[0] = sl[0] / (float)NROWS;
        out[1] = sp[0] / (float)NROWS;
    }
}

// ---------------------------------------------------------------------------
extern "C" void kernel_launch(void* const* d_in, const int* in_sizes, int n_in,
                              void* d_out, int out_size) {
    const float* z = (const float*)d_in[0];
    float* out = (float*)d_out;

    cudaFuncSetAttribute(gemm_kernel, cudaFuncAttributeMaxDynamicSharedMemorySize, SMEM_TOTAL);

    normconv_kernel<<<2 * NROWS / 8, 256>>>(z);
    gemm_kernel<<<dim3(NROWS / BN, NROWS / BM), 256, SMEM_TOTAL>>>();
    finalize1_kernel<<<NROWS / 128, 1024>>>();
    finalize2_kernel<<<1, 64>>>(out);
}